// round 2
// baseline (speedup 1.0000x reference)
#include <cuda_runtime.h>
#include <math.h>

// ---------------- problem constants ----------------
#define B    4
#define LQ   1024
#define LK   2048
#define D    1024
#define H    16
#define HD   64
#define F    4096
#define MQ   (B*LQ)     // 4096
#define MCTX (B*LK)     // 8192

// ---------------- scratch (static __device__, no allocs) ----------------
__device__ float g_q   [(size_t)MQ   * D];          // 16 MB
__device__ float g_k   [(size_t)MCTX * D];          // 32 MB
__device__ float g_v   [(size_t)MCTX * D];          // 32 MB
__device__ float g_att [(size_t)MQ * D];            // 16 MB
__device__ float g_x   [(size_t)MQ * D];            // 16 MB
__device__ float g_x2  [(size_t)MQ * D];            // 16 MB
__device__ float g_y   [(size_t)MQ * D];            // 16 MB
__device__ float g_int [(size_t)MQ * F];            // 64 MB

// ---------------- GEMM: C[M,N] = A[M,K] @ Bw[K,N] + bias, optional GELU ----
// 128x128 block tile, BK=8, 256 threads, 8x8 per-thread microtile.
template<int EPI>  // 0 = bias, 1 = bias + exact gelu
__global__ void __launch_bounds__(256) sgemm_kernel(
    const float* __restrict__ A, const float* __restrict__ Bw,
    const float* __restrict__ bias, float* __restrict__ C,
    int M, int N, int K)
{
    __shared__ float As[8][128];
    __shared__ float Bs[8][128];
    const int tid = threadIdx.x;
    const int tx = tid & 15, ty = tid >> 4;
    const int bm = blockIdx.y * 128, bn = blockIdx.x * 128;

    const int arow = tid >> 1, acol = (tid & 1) * 4;   // A: 128 rows x 8 cols
    const int brow = tid >> 5, bcol = (tid & 31) * 4;  // B: 8 rows x 128 cols

    const float* Ap = A  + (size_t)(bm + arow) * K + acol;
    const float* Bp = Bw + (size_t)brow * N + bn + bcol;

    float acc[8][8];
    #pragma unroll
    for (int i = 0; i < 8; i++)
        #pragma unroll
        for (int j = 0; j < 8; j++) acc[i][j] = 0.f;

    for (int k0 = 0; k0 < K; k0 += 8) {
        float4 a4 = *(const float4*)(Ap + k0);
        float4 b4 = *(const float4*)(Bp + (size_t)k0 * N);
        As[acol+0][arow] = a4.x; As[acol+1][arow] = a4.y;
        As[acol+2][arow] = a4.z; As[acol+3][arow] = a4.w;
        *(float4*)&Bs[brow][bcol] = b4;
        __syncthreads();
        #pragma unroll
        for (int kk = 0; kk < 8; kk++) {
            float ar[8], br[8];
            #pragma unroll
            for (int i = 0; i < 8; i++) ar[i] = As[kk][i*16 + ty];
            #pragma unroll
            for (int j = 0; j < 8; j++) br[j] = Bs[kk][j*16 + tx];
            #pragma unroll
            for (int i = 0; i < 8; i++)
                #pragma unroll
                for (int j = 0; j < 8; j++) acc[i][j] += ar[i] * br[j];
        }
        __syncthreads();
    }

    float bv[8];
    #pragma unroll
    for (int j = 0; j < 8; j++) bv[j] = bias[bn + j*16 + tx];

    #pragma unroll
    for (int i = 0; i < 8; i++) {
        const int row = bm + i*16 + ty;
        #pragma unroll
        for (int j = 0; j < 8; j++) {
            const int col = bn + j*16 + tx;
            float v = acc[i][j] + bv[j];
            if (EPI == 1) v = 0.5f * v * (1.0f + erff(v * 0.70710678118654752f));
            C[(size_t)row * N + col] = v;
        }
    }
}

// ---------------- fused flash attention ----------------
// O[b,q,h*64+d] = softmax_k(scale*Q·K + mask) · V, online softmax.
// grid: (Lq/64, B*H), block 256. BQ=64, BK=32, HD=64.
// Thread map: tx = tid&15 (16), ty = tid>>4 (16).
// Score tile 64x32: s[i][jj] at rows i*16+ty, cols jj*16+tx.
// Output 64x64:     o[i][j]  at rows i*16+ty, dcols j*16+tx.
__global__ void __launch_bounds__(256) flash_attn_kernel(
    const float* __restrict__ Q, const float* __restrict__ Kx,
    const float* __restrict__ V, const float* __restrict__ mask,
    float* __restrict__ O, int Lq, int Lk, float scale)
{
    __shared__ float Qs[64][65];
    __shared__ float Ks[32][65];
    __shared__ float Vs[32][64];
    __shared__ float Ps[64][33];

    const int bh = blockIdx.y;
    const int b = bh >> 4, h = bh & 15;
    const int q0 = blockIdx.x * 64;
    const int tid = threadIdx.x;
    const int tx = tid & 15, ty = tid >> 4;

    // load Q tile (64 rows x 64 d), float4 per thread x4
    #pragma unroll
    for (int it = 0; it < 4; it++) {
        int idx = tid + it * 256;            // 0..1023
        int r = idx >> 4, c4 = (idx & 15) * 4;
        float4 qv = *(const float4*)(Q + ((size_t)(b*Lq + q0 + r)) * D + h*HD + c4);
        Qs[r][c4+0] = qv.x; Qs[r][c4+1] = qv.y; Qs[r][c4+2] = qv.z; Qs[r][c4+3] = qv.w;
    }

    float m[4], l[4], o[4][4];
    #pragma unroll
    for (int i = 0; i < 4; i++) {
        m[i] = -1e30f; l[i] = 0.f;
        #pragma unroll
        for (int j = 0; j < 4; j++) o[i][j] = 0.f;
    }

    for (int k0 = 0; k0 < Lk; k0 += 32) {
        // load K,V tiles: 32 rows x 64 d each = 512 float4, 2 per thread each
        #pragma unroll
        for (int it = 0; it < 2; it++) {
            int idx = tid + it * 256;        // 0..511
            int r = idx >> 4, c4 = (idx & 15) * 4;
            const size_t grow = (size_t)(b*Lk + k0 + r) * D + h*HD + c4;
            float4 kv = *(const float4*)(Kx + grow);
            Ks[r][c4+0] = kv.x; Ks[r][c4+1] = kv.y; Ks[r][c4+2] = kv.z; Ks[r][c4+3] = kv.w;
            float4 vv = *(const float4*)(V + grow);
            *(float4*)&Vs[r][c4] = vv;
        }
        __syncthreads();

        // scores s[4][2]
        float s[4][2] = {};
        #pragma unroll 8
        for (int d = 0; d < 64; d++) {
            float qr[4], kr[2];
            #pragma unroll
            for (int i = 0; i < 4; i++) qr[i] = Qs[i*16 + ty][d];
            #pragma unroll
            for (int jj = 0; jj < 2; jj++) kr[jj] = Ks[jj*16 + tx][d];
            #pragma unroll
            for (int i = 0; i < 4; i++) {
                s[i][0] += qr[i] * kr[0];
                s[i][1] += qr[i] * kr[1];
            }
        }

        // scale + mask
        #pragma unroll
        for (int jj = 0; jj < 2; jj++) {
            float mv = mask ? mask[(size_t)b * Lk + k0 + jj*16 + tx] : 0.f;
            #pragma unroll
            for (int i = 0; i < 4; i++) s[i][jj] = s[i][jj] * scale + mv;
        }

        // online softmax update
        #pragma unroll
        for (int i = 0; i < 4; i++) {
            float tm = fmaxf(s[i][0], s[i][1]);
            #pragma unroll
            for (int sh = 8; sh > 0; sh >>= 1)
                tm = fmaxf(tm, __shfl_xor_sync(0xffffffffu, tm, sh));
            float nm = fmaxf(m[i], tm);
            float corr = __expf(m[i] - nm);
            m[i] = nm;
            float p0 = __expf(s[i][0] - nm);
            float p1 = __expf(s[i][1] - nm);
            float ts = p0 + p1;
            #pragma unroll
            for (int sh = 8; sh > 0; sh >>= 1)
                ts += __shfl_xor_sync(0xffffffffu, ts, sh);
            l[i] = l[i] * corr + ts;
            #pragma unroll
            for (int j = 0; j < 4; j++) o[i][j] *= corr;
            s[i][0] = p0; s[i][1] = p1;
        }

        // stage P
        #pragma unroll
        for (int i = 0; i < 4; i++) {
            Ps[i*16 + ty][tx]      = s[i][0];
            Ps[i*16 + ty][16 + tx] = s[i][1];
        }
        __syncthreads();

        // o += Ps x Vs
        #pragma unroll 8
        for (int kk = 0; kk < 32; kk++) {
            float pr[4], vr[4];
            #pragma unroll
            for (int i = 0; i < 4; i++) pr[i] = Ps[i*16 + ty][kk];
            #pragma unroll
            for (int j = 0; j < 4; j++) vr[j] = Vs[kk][j*16 + tx];
            #pragma unroll
            for (int i = 0; i < 4; i++)
                #pragma unroll
                for (int j = 0; j < 4; j++) o[i][j] += pr[i] * vr[j];
        }
        __syncthreads();
    }

    // normalize + write
    #pragma unroll
    for (int i = 0; i < 4; i++) {
        const float inv = 1.0f / l[i];
        const int q = q0 + i*16 + ty;
        #pragma unroll
        for (int j = 0; j < 4; j++)
            O[((size_t)(b*Lq + q)) * D + h*HD + j*16 + tx] = o[i][j] * inv;
    }
}

// ---------------- residual + LayerNorm: O = LN(Y + R) * g + be -------------
__global__ void __launch_bounds__(256) ln_residual_kernel(
    const float* __restrict__ Y, const float* __restrict__ R,
    const float* __restrict__ g, const float* __restrict__ be,
    float* __restrict__ O)
{
    const size_t row = blockIdx.x;
    const int tid = threadIdx.x;
    const float* y = Y + row * D;
    const float* r = R + row * D;
    __shared__ float red[256];

    float h[4];
    float s = 0.f;
    #pragma unroll
    for (int i = 0; i < 4; i++) {
        h[i] = y[tid + i*256] + r[tid + i*256];
        s += h[i];
    }
    red[tid] = s; __syncthreads();
    for (int st = 128; st > 0; st >>= 1) {
        if (tid < st) red[tid] += red[tid + st];
        __syncthreads();
    }
    const float mean = red[0] * (1.0f / D);
    __syncthreads();

    float vs = 0.f;
    #pragma unroll
    for (int i = 0; i < 4; i++) {
        float dd = h[i] - mean;
        vs += dd * dd;
    }
    red[tid] = vs; __syncthreads();
    for (int st = 128; st > 0; st >>= 1) {
        if (tid < st) red[tid] += red[tid + st];
        __syncthreads();
    }
    const float inv = rsqrtf(red[0] * (1.0f / D) + 1e-5f);

    #pragma unroll
    for (int i = 0; i < 4; i++) {
        const int c = tid + i*256;
        O[row * D + c] = (h[i] - mean) * inv * g[c] + be[c];
    }
}

// ---------------- host launch ----------------
extern "C" void kernel_launch(void* const* d_in, const int* in_sizes, int n_in,
                              void* d_out, int out_size)
{
    const float* input = (const float*)d_in[0];
    const float* ctx   = (const float*)d_in[1];
    const float* mask  = (const float*)d_in[2];
    const float* cq_w = (const float*)d_in[3];  const float* cq_b = (const float*)d_in[4];
    const float* ck_w = (const float*)d_in[5];  const float* ck_b = (const float*)d_in[6];
    const float* cv_w = (const float*)d_in[7];  const float* cv_b = (const float*)d_in[8];
    const float* co_w = (const float*)d_in[9];  const float* co_b = (const float*)d_in[10];
    const float* co_g = (const float*)d_in[11]; const float* co_be= (const float*)d_in[12];
    const float* sq_w = (const float*)d_in[13]; const float* sq_b = (const float*)d_in[14];
    const float* sk_w = (const float*)d_in[15]; const float* sk_b = (const float*)d_in[16];
    const float* sv_w = (const float*)d_in[17]; const float* sv_b = (const float*)d_in[18];
    const float* so_w = (const float*)d_in[19]; const float* so_b = (const float*)d_in[20];
    const float* so_g = (const float*)d_in[21]; const float* so_be= (const float*)d_in[22];
    const float* fi_w = (const float*)d_in[23]; const float* fi_b = (const float*)d_in[24];
    const float* fo_w = (const float*)d_in[25]; const float* fo_b = (const float*)d_in[26];
    const float* fo_g = (const float*)d_in[27]; const float* fo_be= (const float*)d_in[28];

    float *q, *k, *v, *att, *x, *x2, *y, *inter;
    cudaGetSymbolAddress((void**)&q,    g_q);
    cudaGetSymbolAddress((void**)&k,    g_k);
    cudaGetSymbolAddress((void**)&v,    g_v);
    cudaGetSymbolAddress((void**)&att,  g_att);
    cudaGetSymbolAddress((void**)&x,    g_x);
    cudaGetSymbolAddress((void**)&x2,   g_x2);
    cudaGetSymbolAddress((void**)&y,    g_y);
    cudaGetSymbolAddress((void**)&inter,g_int);

    const float scale = 0.125f; // 1/sqrt(64)
    dim3 blk(256);

    // ---- cross attention ----
    sgemm_kernel<0><<<dim3(D/128, MQ/128),   blk>>>(input, cq_w, cq_b, q, MQ,   D, D);
    sgemm_kernel<0><<<dim3(D/128, MCTX/128), blk>>>(ctx,   ck_w, ck_b, k, MCTX, D, D);
    sgemm_kernel<0><<<dim3(D/128, MCTX/128), blk>>>(ctx,   cv_w, cv_b, v, MCTX, D, D);

    flash_attn_kernel<<<dim3(LQ/64, B*H), blk>>>(q, k, v, mask, att, LQ, LK, scale);

    sgemm_kernel<0><<<dim3(D/128, MQ/128), blk>>>(att, co_w, co_b, y, MQ, D, D);
    ln_residual_kernel<<<MQ, blk>>>(y, input, co_g, co_be, x);

    // ---- self attention ----
    sgemm_kernel<0><<<dim3(D/128, MQ/128), blk>>>(x, sq_w, sq_b, q, MQ, D, D);
    sgemm_kernel<0><<<dim3(D/128, MQ/128), blk>>>(x, sk_w, sk_b, k, MQ, D, D);
    sgemm_kernel<0><<<dim3(D/128, MQ/128), blk>>>(x, sv_w, sv_b, v, MQ, D, D);

    flash_attn_kernel<<<dim3(LQ/64, B*H), blk>>>(q, k, v, nullptr, att, LQ, LQ, scale);

    sgemm_kernel<0><<<dim3(D/128, MQ/128), blk>>>(att, so_w, so_b, y, MQ, D, D);
    ln_residual_kernel<<<MQ, blk>>>(y, x, so_g, so_be, x2);

    // ---- FFN ----
    sgemm_kernel<1><<<dim3(F/128, MQ/128), blk>>>(x2, fi_w, fi_b, inter, MQ, F, D);
    sgemm_kernel<0><<<dim3(D/128, MQ/128), blk>>>(inter, fo_w, fo_b, y, MQ, D, F);
    ln_residual_kernel<<<MQ, blk>>>(y, x2, fo_g, fo_be, (float*)d_out);
}

// round 8
// speedup vs baseline: 1.9370x; 1.9370x over previous
#include <cuda_runtime.h>
#include <cuda_bf16.h>
#include <cstdint>
#include <stdint.h>
#include <math.h>

// ---------------- problem constants ----------------
#define B    4
#define LQ   1024
#define LK   2048
#define D    1024
#define H    16
#define HD   64
#define F    4096
#define MQ   (B*LQ)     // 4096
#define MCTX (B*LK)     // 8192

// ---------------- scratch (static __device__, no allocs) ----------------
__device__ float g_q   [(size_t)MQ   * D];
__device__ float g_k   [(size_t)MCTX * D];
__device__ float g_v   [(size_t)MCTX * D];
__device__ float g_att [(size_t)MQ * D];
__device__ float g_x   [(size_t)MQ * D];
__device__ float g_x2  [(size_t)MQ * D];
__device__ float g_y   [(size_t)MQ * D];
__device__ float g_int [(size_t)MQ * F];
__device__ __nv_bfloat16 g_sa [(size_t)MQ * 3 * F];      // A' split buffer (max 4096 x 12288)
__device__ __nv_bfloat16 g_sb [(size_t)3 * F * D];       // B' split buffer (max 12288 x 1024)

// ================= bf16 split conversion =================
// A-side: X[R,C] fp32 -> Y[R,3C] bf16 = [Ah | Ah | Al] per row.
__global__ void __launch_bounds__(256) split_a_kernel(
    const float* __restrict__ X, __nv_bfloat16* __restrict__ Y, int cmask, int cshift)
{
    const size_t i4 = ((size_t)blockIdx.x * 256 + threadIdx.x) * 4;
    const int C = cmask + 1;
    const size_t r = i4 >> cshift;
    const int c = (int)(i4 & cmask);
    float4 x = *(const float4*)(X + i4);

    unsigned short hu[4], lu[4];
    float xs[4] = {x.x, x.y, x.z, x.w};
    #pragma unroll
    for (int t = 0; t < 4; t++) {
        __nv_bfloat16 h = __float2bfloat16(xs[t]);
        __nv_bfloat16 l = __float2bfloat16(xs[t] - __bfloat162float(h));
        hu[t] = *(unsigned short*)&h;
        lu[t] = *(unsigned short*)&l;
    }
    ushort4 h4 = {hu[0], hu[1], hu[2], hu[3]};
    ushort4 l4 = {lu[0], lu[1], lu[2], lu[3]};
    __nv_bfloat16* row = Y + r * (size_t)(3 * C);
    *(ushort4*)(row + c)         = h4;
    *(ushort4*)(row + C + c)     = h4;
    *(ushort4*)(row + 2 * C + c) = l4;
}

// B-side: W[K,N] fp32 -> Y[3K,N] bf16 = [Bh ; Bl ; Bh] (row blocks).
__global__ void __launch_bounds__(256) split_b_kernel(
    const float* __restrict__ W, __nv_bfloat16* __restrict__ Y, int K, int nmask, int nshift)
{
    const size_t i4 = ((size_t)blockIdx.x * 256 + threadIdx.x) * 4;
    const int N = nmask + 1;
    const size_t r = i4 >> nshift;
    const int c = (int)(i4 & nmask);
    float4 x = *(const float4*)(W + i4);

    unsigned short hu[4], lu[4];
    float xs[4] = {x.x, x.y, x.z, x.w};
    #pragma unroll
    for (int t = 0; t < 4; t++) {
        __nv_bfloat16 h = __float2bfloat16(xs[t]);
        __nv_bfloat16 l = __float2bfloat16(xs[t] - __bfloat162float(h));
        hu[t] = *(unsigned short*)&h;
        lu[t] = *(unsigned short*)&l;
    }
    ushort4 h4 = {hu[0], hu[1], hu[2], hu[3]};
    ushort4 l4 = {lu[0], lu[1], lu[2], lu[3]};
    *(ushort4*)(Y + r * (size_t)N + c)             = h4;  // rows [0,K): Bh
    *(ushort4*)(Y + ((size_t)K + r) * N + c)       = l4;  // rows [K,2K): Bl
    *(ushort4*)(Y + ((size_t)(2 * K) + r) * N + c) = h4;  // rows [2K,3K): Bh
}

// ================= bf16 tensor-core GEMM =================
// C[M,N] = A'[M,Kp] @ B'[Kp,N] + bias (+ gelu). BM=BN=128, BK=32, 256 thr, 8 warps (4x2).
__device__ __forceinline__ void cp_async16(void* smem, const void* gmem) {
    unsigned int s = (unsigned int)__cvta_generic_to_shared(smem);
    asm volatile("cp.async.cg.shared.global [%0], [%1], 16;\n" :: "r"(s), "l"(gmem));
}

template<int EPI>  // 0 = bias, 1 = bias + exact gelu
__global__ void __launch_bounds__(256) hgemm_kernel(
    const __nv_bfloat16* __restrict__ A, const __nv_bfloat16* __restrict__ Bw,
    const float* __restrict__ bias, float* __restrict__ C,
    int N, int Kp)
{
    __shared__ __nv_bfloat16 As[2][128][40];
    __shared__ __nv_bfloat16 Bs[2][32][136];

    const int tid  = threadIdx.x;
    const int wid  = tid >> 5, lane = tid & 31;
    const int wm   = (wid >> 1) * 32, wn = (wid & 1) * 64;
    const int bm   = blockIdx.y * 128, bn = blockIdx.x * 128;

    float acc[2][8][4];
    #pragma unroll
    for (int f = 0; f < 2; f++)
        #pragma unroll
        for (int p = 0; p < 8; p++)
            #pragma unroll
            for (int t = 0; t < 4; t++) acc[f][p][t] = 0.f;

    // tile loader
    auto issue_tile = [&](int buf, int k0) {
        #pragma unroll
        for (int t = 0; t < 2; t++) {
            int idx = tid + t * 256;                 // 512 chunks of 16B for A (128x32)
            int ar = idx >> 2, ac = (idx & 3) * 8;
            cp_async16(&As[buf][ar][ac], A + (size_t)(bm + ar) * Kp + k0 + ac);
        }
        #pragma unroll
        for (int t = 0; t < 2; t++) {
            int idx = tid + t * 256;                 // 512 chunks for B (32x128)
            int br = idx >> 4, bc = (idx & 15) * 8;
            cp_async16(&Bs[buf][br][bc], Bw + (size_t)(k0 + br) * N + bn + bc);
        }
        asm volatile("cp.async.commit_group;\n" ::: "memory");
    };

    const int NIT = Kp / 32;
    issue_tile(0, 0);
    int buf = 0;

    for (int it = 0; it < NIT; it++) {
        if (it + 1 < NIT) {
            issue_tile(buf ^ 1, (it + 1) * 32);
            asm volatile("cp.async.wait_group 1;\n" ::: "memory");
        } else {
            asm volatile("cp.async.wait_group 0;\n" ::: "memory");
        }
        __syncthreads();

        #pragma unroll
        for (int kk = 0; kk < 32; kk += 16) {
            unsigned int af[2][4];
            #pragma unroll
            for (int f = 0; f < 2; f++) {
                int row = wm + f * 16 + (lane & 15);
                int col = kk + (lane >> 4) * 8;
                unsigned int addr = (unsigned int)__cvta_generic_to_shared(&As[buf][row][col]);
                asm volatile("ldmatrix.sync.aligned.m8n8.x4.shared.b16 {%0,%1,%2,%3}, [%4];"
                    : "=r"(af[f][0]), "=r"(af[f][1]), "=r"(af[f][2]), "=r"(af[f][3]) : "r"(addr));
            }
            unsigned int bfr[8][2];
            #pragma unroll
            for (int p = 0; p < 4; p++) {
                int krow = kk + (lane & 7) + ((lane >> 3) & 1) * 8;
                int ncol = wn + p * 16 + (lane >> 4) * 8;
                unsigned int addr = (unsigned int)__cvta_generic_to_shared(&Bs[buf][krow][ncol]);
                unsigned int r0, r1, r2, r3;
                asm volatile("ldmatrix.sync.aligned.m8n8.x4.trans.shared.b16 {%0,%1,%2,%3}, [%4];"
                    : "=r"(r0), "=r"(r1), "=r"(r2), "=r"(r3) : "r"(addr));
                bfr[p*2][0] = r0; bfr[p*2][1] = r1; bfr[p*2+1][0] = r2; bfr[p*2+1][1] = r3;
            }
            #pragma unroll
            for (int f = 0; f < 2; f++)
                #pragma unroll
                for (int p = 0; p < 8; p++)
                    asm volatile(
                        "mma.sync.aligned.m16n8k16.row.col.f32.bf16.bf16.f32 "
                        "{%0,%1,%2,%3},{%4,%5,%6,%7},{%8,%9},{%0,%1,%2,%3};"
                        : "+f"(acc[f][p][0]), "+f"(acc[f][p][1]),
                          "+f"(acc[f][p][2]), "+f"(acc[f][p][3])
                        : "r"(af[f][0]), "r"(af[f][1]), "r"(af[f][2]), "r"(af[f][3]),
                          "r"(bfr[p][0]), "r"(bfr[p][1]));
        }
        __syncthreads();
        buf ^= 1;
    }

    // epilogue
    const int r0 = lane >> 2, c0 = (lane & 3) * 2;
    #pragma unroll
    for (int f = 0; f < 2; f++) {
        #pragma unroll
        for (int p = 0; p < 8; p++) {
            const int grow = bm + wm + f * 16 + r0;
            const int gcol = bn + wn + p * 8 + c0;
            const float b0 = bias[gcol], b1 = bias[gcol + 1];
            float v00 = acc[f][p][0] + b0, v01 = acc[f][p][1] + b1;
            float v10 = acc[f][p][2] + b0, v11 = acc[f][p][3] + b1;
            if (EPI == 1) {
                v00 = 0.5f * v00 * (1.0f + erff(v00 * 0.70710678118654752f));
                v01 = 0.5f * v01 * (1.0f + erff(v01 * 0.70710678118654752f));
                v10 = 0.5f * v10 * (1.0f + erff(v10 * 0.70710678118654752f));
                v11 = 0.5f * v11 * (1.0f + erff(v11 * 0.70710678118654752f));
            }
            float2 lo = {v00, v01}, hi = {v10, v11};
            *(float2*)(C + (size_t)grow * N + gcol)       = lo;
            *(float2*)(C + (size_t)(grow + 8) * N + gcol) = hi;
        }
    }
}

// ================= fused flash attention (fp32, vectorized smem) =================
__global__ void __launch_bounds__(256) flash_attn_kernel(
    const float* __restrict__ Q, const float* __restrict__ Kx,
    const float* __restrict__ V, const float* __restrict__ mask,
    float* __restrict__ O, int Lq, int Lk, float scale)
{
    __shared__ float Qs[64][68];
    __shared__ float Ks[32][68];
    __shared__ float Vs[32][64];
    __shared__ float Ps[64][36];

    const int bh = blockIdx.y;
    const int b = bh >> 4, h = bh & 15;
    const int q0 = blockIdx.x * 64;
    const int tid = threadIdx.x;
    const int tx = tid & 15, ty = tid >> 4;

    #pragma unroll
    for (int it = 0; it < 4; it++) {
        int idx = tid + it * 256;
        int r = idx >> 4, c4 = (idx & 15) * 4;
        float4 qv = *(const float4*)(Q + ((size_t)(b*Lq + q0 + r)) * D + h*HD + c4);
        *(float4*)&Qs[r][c4] = qv;
    }

    float m[4], l[4], o[4][4];
    #pragma unroll
    for (int i = 0; i < 4; i++) {
        m[i] = -1e30f; l[i] = 0.f;
        #pragma unroll
        for (int j = 0; j < 4; j++) o[i][j] = 0.f;
    }

    for (int k0 = 0; k0 < Lk; k0 += 32) {
        #pragma unroll
        for (int it = 0; it < 2; it++) {
            int idx = tid + it * 256;
            int r = idx >> 4, c4 = (idx & 15) * 4;
            const size_t grow = (size_t)(b*Lk + k0 + r) * D + h*HD + c4;
            *(float4*)&Ks[r][c4] = *(const float4*)(Kx + grow);
            *(float4*)&Vs[r][c4] = *(const float4*)(V + grow);
        }
        __syncthreads();

        // scores: s[4][2], vectorized over d
        float s[4][2] = {};
        #pragma unroll
        for (int d4 = 0; d4 < 64; d4 += 4) {
            float4 q4[4], k4[2];
            #pragma unroll
            for (int i = 0; i < 4; i++) q4[i] = *(const float4*)&Qs[i*16 + ty][d4];
            #pragma unroll
            for (int jj = 0; jj < 2; jj++) k4[jj] = *(const float4*)&Ks[jj*16 + tx][d4];
            #pragma unroll
            for (int i = 0; i < 4; i++)
                #pragma unroll
                for (int jj = 0; jj < 2; jj++)
                    s[i][jj] += q4[i].x*k4[jj].x + q4[i].y*k4[jj].y
                              + q4[i].z*k4[jj].z + q4[i].w*k4[jj].w;
        }

        #pragma unroll
        for (int jj = 0; jj < 2; jj++) {
            float mv = mask ? mask[(size_t)b * Lk + k0 + jj*16 + tx] : 0.f;
            #pragma unroll
            for (int i = 0; i < 4; i++) s[i][jj] = s[i][jj] * scale + mv;
        }

        #pragma unroll
        for (int i = 0; i < 4; i++) {
            float tm = fmaxf(s[i][0], s[i][1]);
            #pragma unroll
            for (int sh = 8; sh > 0; sh >>= 1)
                tm = fmaxf(tm, __shfl_xor_sync(0xffffffffu, tm, sh));
            float nm = fmaxf(m[i], tm);
            float corr = __expf(m[i] - nm);
            m[i] = nm;
            float p0 = __expf(s[i][0] - nm);
            float p1 = __expf(s[i][1] - nm);
            float ts = p0 + p1;
            #pragma unroll
            for (int sh = 8; sh > 0; sh >>= 1)
                ts += __shfl_xor_sync(0xffffffffu, ts, sh);
            l[i] = l[i] * corr + ts;
            #pragma unroll
            for (int j = 0; j < 4; j++) o[i][j] *= corr;
            s[i][0] = p0; s[i][1] = p1;
        }

        #pragma unroll
        for (int i = 0; i < 4; i++) {
            Ps[i*16 + ty][tx]      = s[i][0];
            Ps[i*16 + ty][16 + tx] = s[i][1];
        }
        __syncthreads();

        // o += Ps x Vs, P vectorized over k
        #pragma unroll
        for (int kk4 = 0; kk4 < 32; kk4 += 4) {
            float pr[4][4];
            #pragma unroll
            for (int i = 0; i < 4; i++)
                *(float4*)pr[i] = *(const float4*)&Ps[i*16 + ty][kk4];
            #pragma unroll
            for (int t = 0; t < 4; t++) {
                float vr[4];
                #pragma unroll
                for (int j = 0; j < 4; j++) vr[j] = Vs[kk4 + t][j*16 + tx];
                #pragma unroll
                for (int i = 0; i < 4; i++)
                    #pragma unroll
                    for (int j = 0; j < 4; j++) o[i][j] += pr[i][t] * vr[j];
            }
        }
        __syncthreads();
    }

    #pragma unroll
    for (int i = 0; i < 4; i++) {
        const float inv = 1.0f / l[i];
        const int q = q0 + i*16 + ty;
        #pragma unroll
        for (int j = 0; j < 4; j++)
            O[((size_t)(b*Lq + q)) * D + h*HD + j*16 + tx] = o[i][j] * inv;
    }
}

// ================= residual + LayerNorm =================
__global__ void __launch_bounds__(256) ln_residual_kernel(
    const float* __restrict__ Y, const float* __restrict__ R,
    const float* __restrict__ g, const float* __restrict__ be,
    float* __restrict__ O)
{
    const size_t row = blockIdx.x;
    const int tid = threadIdx.x;
    const float* y = Y + row * D;
    const float* r = R + row * D;
    __shared__ float red[256];

    float h[4];
    float s = 0.f;
    #pragma unroll
    for (int i = 0; i < 4; i++) {
        h[i] = y[tid + i*256] + r[tid + i*256];
        s += h[i];
    }
    red[tid] = s; __syncthreads();
    for (int st = 128; st > 0; st >>= 1) {
        if (tid < st) red[tid] += red[tid + st];
        __syncthreads();
    }
    const float mean = red[0] * (1.0f / D);
    __syncthreads();

    float vs = 0.f;
    #pragma unroll
    for (int i = 0; i < 4; i++) {
        float dd = h[i] - mean;
        vs += dd * dd;
    }
    red[tid] = vs; __syncthreads();
    for (int st = 128; st > 0; st >>= 1) {
        if (tid < st) red[tid] += red[tid + st];
        __syncthreads();
    }
    const float inv = rsqrtf(red[0] * (1.0f / D) + 1e-5f);

    #pragma unroll
    for (int i = 0; i < 4; i++) {
        const int c = tid + i*256;
        O[row * D + c] = (h[i] - mean) * inv * g[c] + be[c];
    }
}

// ================= host launch =================
extern "C" void kernel_launch(void* const* d_in, const int* in_sizes, int n_in,
                              void* d_out, int out_size)
{
    const float* input = (const float*)d_in[0];
    const float* ctx   = (const float*)d_in[1];
    const float* mask  = (const float*)d_in[2];
    const float* cq_w = (const float*)d_in[3];  const float* cq_b = (const float*)d_in[4];
    const float* ck_w = (const float*)d_in[5];  const float* ck_b = (const float*)d_in[6];
    const float* cv_w = (const float*)d_in[7];  const float* cv_b = (const float*)d_in[8];
    const float* co_w = (const float*)d_in[9];  const float* co_b = (const float*)d_in[10];
    const float* co_g = (const float*)d_in[11]; const float* co_be= (const float*)d_in[12];
    const float* sq_w = (const float*)d_in[13]; const float* sq_b = (const float*)d_in[14];
    const float* sk_w = (const float*)d_in[15]; const float* sk_b = (const float*)d_in[16];
    const float* sv_w = (const float*)d_in[17]; const float* sv_b = (const float*)d_in[18];
    const float* so_w = (const float*)d_in[19]; const float* so_b = (const float*)d_in[20];
    const float* so_g = (const float*)d_in[21]; const float* so_be= (const float*)d_in[22];
    const float* fi_w = (const float*)d_in[23]; const float* fi_b = (const float*)d_in[24];
    const float* fo_w = (const float*)d_in[25]; const float* fo_b = (const float*)d_in[26];
    const float* fo_g = (const float*)d_in[27]; const float* fo_be= (const float*)d_in[28];

    float *q, *k, *v, *att, *x, *x2, *y, *inter;
    __nv_bfloat16 *sa, *sb;
    cudaGetSymbolAddress((void**)&q,    g_q);
    cudaGetSymbolAddress((void**)&k,    g_k);
    cudaGetSymbolAddress((void**)&v,    g_v);
    cudaGetSymbolAddress((void**)&att,  g_att);
    cudaGetSymbolAddress((void**)&x,    g_x);
    cudaGetSymbolAddress((void**)&x2,   g_x2);
    cudaGetSymbolAddress((void**)&y,    g_y);
    cudaGetSymbolAddress((void**)&inter,g_int);
    cudaGetSymbolAddress((void**)&sa,   g_sa);
    cudaGetSymbolAddress((void**)&sb,   g_sb);

    const float scale = 0.125f; // 1/sqrt(64)
    dim3 blk(256);

    // split helpers: grid = elems/1024 (256 thr x 4 elems)
    #define SPLIT_A(X, R, C, SH)  split_a_kernel<<<((size_t)(R)*(C))/1024, blk>>>((X), sa, (C)-1, (SH))
    #define SPLIT_B(W, K_, N_, SH) split_b_kernel<<<((size_t)(K_)*(N_))/1024, blk>>>((W), sb, (K_), (N_)-1, (SH))
    #define GEMM(EPI, BIAS, OUT, M_, N_, K3)  hgemm_kernel<EPI><<<dim3((N_)/128, (M_)/128), blk>>>(sa, sb, (BIAS), (OUT), (N_), (K3))

    // ---- cross attention ----
    SPLIT_A(input, MQ, D, 10);
    SPLIT_B(cq_w, D, D, 10);  GEMM(0, cq_b, q, MQ, D, 3*D);
    SPLIT_A(ctx, MCTX, D, 10);
    SPLIT_B(ck_w, D, D, 10);  GEMM(0, ck_b, k, MCTX, D, 3*D);
    SPLIT_B(cv_w, D, D, 10);  GEMM(0, cv_b, v, MCTX, D, 3*D);

    flash_attn_kernel<<<dim3(LQ/64, B*H), blk>>>(q, k, v, mask, att, LQ, LK, scale);

    SPLIT_A(att, MQ, D, 10);
    SPLIT_B(co_w, D, D, 10);  GEMM(0, co_b, y, MQ, D, 3*D);
    ln_residual_kernel<<<MQ, blk>>>(y, input, co_g, co_be, x);

    // ---- self attention ----
    SPLIT_A(x, MQ, D, 10);
    SPLIT_B(sq_w, D, D, 10);  GEMM(0, sq_b, q, MQ, D, 3*D);
    SPLIT_B(sk_w, D, D, 10);  GEMM(0, sk_b, k, MQ, D, 3*D);
    SPLIT_B(sv_w, D, D, 10);  GEMM(0, sv_b, v, MQ, D, 3*D);

    flash_attn_kernel<<<dim3(LQ/64, B*H), blk>>>(q, k, v, nullptr, att, LQ, LQ, scale);

    SPLIT_A(att, MQ, D, 10);
    SPLIT_B(so_w, D, D, 10);  GEMM(0, so_b, y, MQ, D, 3*D);
    ln_residual_kernel<<<MQ, blk>>>(y, x, so_g, so_be, x2);

    // ---- FFN ----
    SPLIT_A(x2, MQ, D, 10);
    SPLIT_B(fi_w, D, F, 12);  GEMM(1, fi_b, inter, MQ, F, 3*D);
    SPLIT_A(inter, MQ, F, 12);
    SPLIT_B(fo_w, F, D, 10);  GEMM(0, fo_b, y, MQ, D, 3*F);
    ln_residual_kernel<<<MQ, blk>>>(y, x2, fo_g, fo_be, (float*)d_out);

    #undef SPLIT_A
    #undef SPLIT_B
    #undef GEMM
}

// round 9
// speedup vs baseline: 2.7700x; 1.4301x over previous
#include <cuda_runtime.h>
#include <cuda_bf16.h>
#include <cstdint>
#include <stdint.h>
#include <math.h>

// ---------------- problem constants ----------------
#define B    4
#define LQ   1024
#define LK   2048
#define D    1024
#define H    16
#define HD   64
#define F    4096
#define MQ   (B*LQ)     // 4096
#define MCTX (B*LK)     // 8192

// ---------------- scratch (static __device__, no allocs) ----------------
__device__ float g_q   [(size_t)MQ   * D];
__device__ float g_k   [(size_t)MCTX * D];
__device__ float g_v   [(size_t)MCTX * D];
__device__ float g_att [(size_t)MQ * D];
__device__ float g_x   [(size_t)MQ * D];
__device__ float g_x2  [(size_t)MQ * D];
__device__ float g_y   [(size_t)MQ * D];
__device__ float g_int [(size_t)MQ * F];
__device__ __nv_bfloat16 g_sa [(size_t)MQ * 3 * F];      // A' split buffer
__device__ __nv_bfloat16 g_sb [(size_t)3 * F * D];       // B' split buffer

// ---------------- asm helpers ----------------
#define LDSM4(R0,R1,R2,R3,PTR) do { \
    unsigned _a = (unsigned)__cvta_generic_to_shared(PTR); \
    asm volatile("ldmatrix.sync.aligned.m8n8.x4.shared.b16 {%0,%1,%2,%3}, [%4];" \
        : "=r"(R0),"=r"(R1),"=r"(R2),"=r"(R3) : "r"(_a)); } while(0)

#define LDSM4T(R0,R1,R2,R3,PTR) do { \
    unsigned _a = (unsigned)__cvta_generic_to_shared(PTR); \
    asm volatile("ldmatrix.sync.aligned.m8n8.x4.trans.shared.b16 {%0,%1,%2,%3}, [%4];" \
        : "=r"(R0),"=r"(R1),"=r"(R2),"=r"(R3) : "r"(_a)); } while(0)

#define MMA16816(C,A0,A1,A2,A3,B0,B1) \
    asm volatile("mma.sync.aligned.m16n8k16.row.col.f32.bf16.bf16.f32 " \
        "{%0,%1,%2,%3},{%4,%5,%6,%7},{%8,%9},{%0,%1,%2,%3};" \
        : "+f"((C)[0]), "+f"((C)[1]), "+f"((C)[2]), "+f"((C)[3]) \
        : "r"(A0), "r"(A1), "r"(A2), "r"(A3), "r"(B0), "r"(B1))

__device__ __forceinline__ void split4(const float4 v, ushort4& h4, ushort4& l4) {
    float xs[4] = {v.x, v.y, v.z, v.w};
    unsigned short hu[4], lu[4];
    #pragma unroll
    for (int t = 0; t < 4; t++) {
        __nv_bfloat16 hh = __float2bfloat16(xs[t]);
        __nv_bfloat16 ll = __float2bfloat16(xs[t] - __bfloat162float(hh));
        hu[t] = *(unsigned short*)&hh; lu[t] = *(unsigned short*)&ll;
    }
    h4.x = hu[0]; h4.y = hu[1]; h4.z = hu[2]; h4.w = hu[3];
    l4.x = lu[0]; l4.y = lu[1]; l4.z = lu[2]; l4.w = lu[3];
}

// ================= bf16 split conversion (GEMM operands) =================
__global__ void __launch_bounds__(256) split_a_kernel(
    const float* __restrict__ X, __nv_bfloat16* __restrict__ Y, int cmask, int cshift)
{
    const size_t i4 = ((size_t)blockIdx.x * 256 + threadIdx.x) * 4;
    const int C = cmask + 1;
    const size_t r = i4 >> cshift;
    const int c = (int)(i4 & cmask);
    ushort4 h4, l4;
    split4(*(const float4*)(X + i4), h4, l4);
    __nv_bfloat16* row = Y + r * (size_t)(3 * C);
    *(ushort4*)(row + c)         = h4;
    *(ushort4*)(row + C + c)     = h4;
    *(ushort4*)(row + 2 * C + c) = l4;
}

__global__ void __launch_bounds__(256) split_b_kernel(
    const float* __restrict__ W, __nv_bfloat16* __restrict__ Y, int K, int nmask, int nshift)
{
    const size_t i4 = ((size_t)blockIdx.x * 256 + threadIdx.x) * 4;
    const int N = nmask + 1;
    const size_t r = i4 >> nshift;
    const int c = (int)(i4 & nmask);
    ushort4 h4, l4;
    split4(*(const float4*)(W + i4), h4, l4);
    *(ushort4*)(Y + r * (size_t)N + c)             = h4;  // Bh
    *(ushort4*)(Y + ((size_t)K + r) * N + c)       = l4;  // Bl
    *(ushort4*)(Y + ((size_t)(2 * K) + r) * N + c) = h4;  // Bh
}

// ================= bf16 tensor-core GEMM =================
__device__ __forceinline__ void cp_async16(void* smem, const void* gmem) {
    unsigned int s = (unsigned int)__cvta_generic_to_shared(smem);
    asm volatile("cp.async.cg.shared.global [%0], [%1], 16;\n" :: "r"(s), "l"(gmem));
}

template<int EPI>  // 0 = bias, 1 = bias + exact gelu
__global__ void __launch_bounds__(256) hgemm_kernel(
    const __nv_bfloat16* __restrict__ A, const __nv_bfloat16* __restrict__ Bw,
    const float* __restrict__ bias, float* __restrict__ C,
    int N, int Kp)
{
    __shared__ __nv_bfloat16 As[2][128][40];
    __shared__ __nv_bfloat16 Bs[2][32][136];

    const int tid  = threadIdx.x;
    const int wid  = tid >> 5, lane = tid & 31;
    const int wm   = (wid >> 1) * 32, wn = (wid & 1) * 64;
    const int bm   = blockIdx.y * 128, bn = blockIdx.x * 128;

    float acc[2][8][4];
    #pragma unroll
    for (int f = 0; f < 2; f++)
        #pragma unroll
        for (int p = 0; p < 8; p++)
            #pragma unroll
            for (int t = 0; t < 4; t++) acc[f][p][t] = 0.f;

    auto issue_tile = [&](int buf, int k0) {
        #pragma unroll
        for (int t = 0; t < 2; t++) {
            int idx = tid + t * 256;
            int ar = idx >> 2, ac = (idx & 3) * 8;
            cp_async16(&As[buf][ar][ac], A + (size_t)(bm + ar) * Kp + k0 + ac);
        }
        #pragma unroll
        for (int t = 0; t < 2; t++) {
            int idx = tid + t * 256;
            int br = idx >> 4, bc = (idx & 15) * 8;
            cp_async16(&Bs[buf][br][bc], Bw + (size_t)(k0 + br) * N + bn + bc);
        }
        asm volatile("cp.async.commit_group;\n" ::: "memory");
    };

    const int NIT = Kp / 32;
    issue_tile(0, 0);
    int buf = 0;

    for (int it = 0; it < NIT; it++) {
        if (it + 1 < NIT) {
            issue_tile(buf ^ 1, (it + 1) * 32);
            asm volatile("cp.async.wait_group 1;\n" ::: "memory");
        } else {
            asm volatile("cp.async.wait_group 0;\n" ::: "memory");
        }
        __syncthreads();

        #pragma unroll
        for (int kk = 0; kk < 32; kk += 16) {
            unsigned int af[2][4];
            #pragma unroll
            for (int f = 0; f < 2; f++) {
                int row = wm + f * 16 + (lane & 15);
                int col = kk + (lane >> 4) * 8;
                LDSM4(af[f][0], af[f][1], af[f][2], af[f][3], &As[buf][row][col]);
            }
            unsigned int bfr[8][2];
            #pragma unroll
            for (int p = 0; p < 4; p++) {
                int krow = kk + (lane & 7) + ((lane >> 3) & 1) * 8;
                int ncol = wn + p * 16 + (lane >> 4) * 8;
                unsigned int r0, r1, r2, r3;
                LDSM4T(r0, r1, r2, r3, &Bs[buf][krow][ncol]);
                bfr[p*2][0] = r0; bfr[p*2][1] = r1; bfr[p*2+1][0] = r2; bfr[p*2+1][1] = r3;
            }
            #pragma unroll
            for (int f = 0; f < 2; f++)
                #pragma unroll
                for (int p = 0; p < 8; p++)
                    MMA16816(acc[f][p], af[f][0], af[f][1], af[f][2], af[f][3],
                             bfr[p][0], bfr[p][1]);
        }
        __syncthreads();
        buf ^= 1;
    }

    const int r0 = lane >> 2, c0 = (lane & 3) * 2;
    #pragma unroll
    for (int f = 0; f < 2; f++) {
        #pragma unroll
        for (int p = 0; p < 8; p++) {
            const int grow = bm + wm + f * 16 + r0;
            const int gcol = bn + wn + p * 8 + c0;
            const float b0 = bias[gcol], b1 = bias[gcol + 1];
            float v00 = acc[f][p][0] + b0, v01 = acc[f][p][1] + b1;
            float v10 = acc[f][p][2] + b0, v11 = acc[f][p][3] + b1;
            if (EPI == 1) {
                v00 = 0.5f * v00 * (1.0f + erff(v00 * 0.70710678118654752f));
                v01 = 0.5f * v01 * (1.0f + erff(v01 * 0.70710678118654752f));
                v10 = 0.5f * v10 * (1.0f + erff(v10 * 0.70710678118654752f));
                v11 = 0.5f * v11 * (1.0f + erff(v11 * 0.70710678118654752f));
            }
            float2 lo = {v00, v01}, hi = {v10, v11};
            *(float2*)(C + (size_t)grow * N + gcol)       = lo;
            *(float2*)(C + (size_t)(grow + 8) * N + gcol) = hi;
        }
    }
}

// ================= tensor-core flash attention =================
// BQ=128, BK=32, 8 warps. Split-bf16: scores = QhKh + QhKl + QlKh,
// PV = PhVh + PlVh + PhVl. Warp w owns q-rows [16w,16w+16), all keys/dims.
struct FlashSmem {
    __nv_bfloat16 Q2[128][136];  // cols [0:64) Qh, [64:128) Ql
    __nv_bfloat16 K2[32][136];   // cols [0:64) Kh, [64:128) Kl
    __nv_bfloat16 V2[64][72];    // rows [0:32) Vh, [32:64) Vl   ([k][d])
    __nv_bfloat16 P2[128][72];   // cols [0:32) Ph, [32:64) Pl
    float msk[32];
};

__global__ void __launch_bounds__(256) flash_attn_tc_kernel(
    const float* __restrict__ Q, const float* __restrict__ Kx,
    const float* __restrict__ V, const float* __restrict__ mask,
    float* __restrict__ O, int Lq, int Lk, float scale)
{
    extern __shared__ char fsm_raw[];
    FlashSmem* sm = (FlashSmem*)fsm_raw;

    const int bh = blockIdx.y;
    const int b = bh >> 4, h = bh & 15;
    const int q0 = blockIdx.x * 128;
    const int tid = threadIdx.x, wid = tid >> 5, lane = tid & 31;
    const int r0 = lane >> 2;          // row within warp strip (and +8)
    const int cc = (lane & 3) * 2;     // col pair base within n8 block

    // ---- load + split Q tile (128 x 64) ----
    #pragma unroll
    for (int it = 0; it < 8; it++) {
        int idx = tid + it * 256;              // 0..2047
        int r = idx >> 4, c4 = (idx & 15) * 4;
        float4 qv = *(const float4*)(Q + (size_t)(b*Lq + q0 + r) * D + h*HD + c4);
        ushort4 h4, l4; split4(qv, h4, l4);
        *(ushort4*)&sm->Q2[r][c4]      = h4;
        *(ushort4*)&sm->Q2[r][64 + c4] = l4;
    }

    float m0 = -1e30f, m1 = -1e30f, l0 = 0.f, l1 = 0.f;
    float o[8][4];
    #pragma unroll
    for (int d = 0; d < 8; d++)
        #pragma unroll
        for (int t = 0; t < 4; t++) o[d][t] = 0.f;

    for (int k0 = 0; k0 < Lk; k0 += 32) {
        __syncthreads();   // previous iteration's smem reads complete

        // ---- load + split K,V tile (32 x 64 each) ----
        #pragma unroll
        for (int it = 0; it < 2; it++) {
            int idx = tid + it * 256;          // 0..511
            int r = idx >> 4, c4 = (idx & 15) * 4;
            const size_t g = (size_t)(b*Lk + k0 + r) * D + h*HD + c4;
            ushort4 h4, l4;
            split4(*(const float4*)(Kx + g), h4, l4);
            *(ushort4*)&sm->K2[r][c4]      = h4;
            *(ushort4*)&sm->K2[r][64 + c4] = l4;
            split4(*(const float4*)(V + g), h4, l4);
            *(ushort4*)&sm->V2[r][c4]      = h4;
            *(ushort4*)&sm->V2[32 + r][c4] = l4;
        }
        if (tid < 32) sm->msk[tid] = mask ? mask[(size_t)b * Lk + k0 + tid] : 0.f;
        __syncthreads();

        // ---- scores: S (16 x 32 per warp), 3-term split over k'=128 ----
        float sf[4][4];
        #pragma unroll
        for (int nb = 0; nb < 4; nb++)
            #pragma unroll
            for (int t = 0; t < 4; t++) sf[nb][t] = 0.f;

        const int qc[12] = {0,16,32,48, 0,16,32,48, 64,80,96,112};
        const int kc[12] = {0,16,32,48, 64,80,96,112, 0,16,32,48};
        #pragma unroll
        for (int s = 0; s < 12; s++) {
            unsigned af[4];
            LDSM4(af[0], af[1], af[2], af[3],
                  &sm->Q2[wid*16 + (lane & 15)][qc[s] + (lane >> 4) * 8]);
            #pragma unroll
            for (int nb = 0; nb < 2; nb++) {
                unsigned t0, t1, t2, t3;
                LDSM4(t0, t1, t2, t3,
                      &sm->K2[nb*16 + (lane & 15)][kc[s] + (lane >> 4) * 8]);
                MMA16816(sf[nb*2],     af[0], af[1], af[2], af[3], t0, t2);
                MMA16816(sf[nb*2 + 1], af[0], af[1], af[2], af[3], t1, t3);
            }
        }

        // ---- scale + mask ----
        #pragma unroll
        for (int nb = 0; nb < 4; nb++) {
            float mv0 = sm->msk[nb*8 + cc], mv1 = sm->msk[nb*8 + cc + 1];
            sf[nb][0] = sf[nb][0] * scale + mv0;
            sf[nb][1] = sf[nb][1] * scale + mv1;
            sf[nb][2] = sf[nb][2] * scale + mv0;
            sf[nb][3] = sf[nb][3] * scale + mv1;
        }

        // ---- online softmax (rows r0, r0+8; quad shuffle reductions) ----
        float tm0 = -1e30f, tm1 = -1e30f;
        #pragma unroll
        for (int nb = 0; nb < 4; nb++) {
            tm0 = fmaxf(tm0, fmaxf(sf[nb][0], sf[nb][1]));
            tm1 = fmaxf(tm1, fmaxf(sf[nb][2], sf[nb][3]));
        }
        tm0 = fmaxf(tm0, __shfl_xor_sync(0xffffffffu, tm0, 1));
        tm0 = fmaxf(tm0, __shfl_xor_sync(0xffffffffu, tm0, 2));
        tm1 = fmaxf(tm1, __shfl_xor_sync(0xffffffffu, tm1, 1));
        tm1 = fmaxf(tm1, __shfl_xor_sync(0xffffffffu, tm1, 2));

        const float nm0 = fmaxf(m0, tm0), nm1 = fmaxf(m1, tm1);
        const float corr0 = __expf(m0 - nm0), corr1 = __expf(m1 - nm1);
        m0 = nm0; m1 = nm1;

        float ts0 = 0.f, ts1 = 0.f;
        #pragma unroll
        for (int nb = 0; nb < 4; nb++) {
            sf[nb][0] = __expf(sf[nb][0] - nm0);
            sf[nb][1] = __expf(sf[nb][1] - nm0);
            sf[nb][2] = __expf(sf[nb][2] - nm1);
            sf[nb][3] = __expf(sf[nb][3] - nm1);
            ts0 += sf[nb][0] + sf[nb][1];
            ts1 += sf[nb][2] + sf[nb][3];
        }
        ts0 += __shfl_xor_sync(0xffffffffu, ts0, 1);
        ts0 += __shfl_xor_sync(0xffffffffu, ts0, 2);
        ts1 += __shfl_xor_sync(0xffffffffu, ts1, 1);
        ts1 += __shfl_xor_sync(0xffffffffu, ts1, 2);
        l0 = l0 * corr0 + ts0;
        l1 = l1 * corr1 + ts1;

        // ---- write split P to smem ----
        const int pr0 = wid*16 + r0, pr1 = pr0 + 8;
        #pragma unroll
        for (int nb = 0; nb < 4; nb++) {
            #pragma unroll
            for (int half = 0; half < 2; half++) {
                const int prow = half ? pr1 : pr0;
                float p0 = sf[nb][half*2], p1 = sf[nb][half*2 + 1];
                __nv_bfloat16 h0 = __float2bfloat16(p0);
                __nv_bfloat16 h1 = __float2bfloat16(p1);
                __nv_bfloat16 e0 = __float2bfloat16(p0 - __bfloat162float(h0));
                __nv_bfloat16 e1 = __float2bfloat16(p1 - __bfloat162float(h1));
                unsigned ph = (unsigned)*(unsigned short*)&h0 |
                              ((unsigned)*(unsigned short*)&h1 << 16);
                unsigned pl = (unsigned)*(unsigned short*)&e0 |
                              ((unsigned)*(unsigned short*)&e1 << 16);
                *(unsigned*)&sm->P2[prow][nb*8 + cc]      = ph;
                *(unsigned*)&sm->P2[prow][32 + nb*8 + cc] = pl;
            }
        }

        // ---- rescale O accumulators ----
        #pragma unroll
        for (int d = 0; d < 8; d++) {
            o[d][0] *= corr0; o[d][1] *= corr0;
            o[d][2] *= corr1; o[d][3] *= corr1;
        }
        __syncthreads();

        // ---- O += P' x V' (3-term, contraction 96) ----
        const int pc[6] = {0, 16, 32, 48, 0, 16};
        const int vc[6] = {0, 16, 0, 16, 32, 48};
        #pragma unroll
        for (int s = 0; s < 6; s++) {
            unsigned af[4];
            LDSM4(af[0], af[1], af[2], af[3],
                  &sm->P2[wid*16 + (lane & 15)][pc[s] + (lane >> 4) * 8]);
            #pragma unroll
            for (int p = 0; p < 4; p++) {
                unsigned t0, t1, t2, t3;
                int krow = vc[s] + (lane & 7) + ((lane >> 3) & 1) * 8;
                int ncol = p*16 + (lane >> 4) * 8;
                LDSM4T(t0, t1, t2, t3, &sm->V2[krow][ncol]);
                MMA16816(o[p*2],     af[0], af[1], af[2], af[3], t0, t1);
                MMA16816(o[p*2 + 1], af[0], af[1], af[2], af[3], t2, t3);
            }
        }
    }

    // ---- normalize + write ----
    const float li0 = 1.f / l0, li1 = 1.f / l1;
    const int gq0 = b*Lq + q0 + wid*16 + r0;
    #pragma unroll
    for (int d = 0; d < 8; d++) {
        float2 v0 = {o[d][0] * li0, o[d][1] * li0};
        float2 v1 = {o[d][2] * li1, o[d][3] * li1};
        *(float2*)(O + (size_t)gq0 * D + h*HD + d*8 + cc)       = v0;
        *(float2*)(O + (size_t)(gq0 + 8) * D + h*HD + d*8 + cc) = v1;
    }
}

// ================= residual + LayerNorm =================
__global__ void __launch_bounds__(256) ln_residual_kernel(
    const float* __restrict__ Y, const float* __restrict__ R,
    const float* __restrict__ g, const float* __restrict__ be,
    float* __restrict__ O)
{
    const size_t row = blockIdx.x;
    const int tid = threadIdx.x;
    const float* y = Y + row * D;
    const float* r = R + row * D;
    __shared__ float red[256];

    float h[4];
    float s = 0.f;
    #pragma unroll
    for (int i = 0; i < 4; i++) {
        h[i] = y[tid + i*256] + r[tid + i*256];
        s += h[i];
    }
    red[tid] = s; __syncthreads();
    for (int st = 128; st > 0; st >>= 1) {
        if (tid < st) red[tid] += red[tid + st];
        __syncthreads();
    }
    const float mean = red[0] * (1.0f / D);
    __syncthreads();

    float vs = 0.f;
    #pragma unroll
    for (int i = 0; i < 4; i++) {
        float dd = h[i] - mean;
        vs += dd * dd;
    }
    red[tid] = vs; __syncthreads();
    for (int st = 128; st > 0; st >>= 1) {
        if (tid < st) red[tid] += red[tid + st];
        __syncthreads();
    }
    const float inv = rsqrtf(red[0] * (1.0f / D) + 1e-5f);

    #pragma unroll
    for (int i = 0; i < 4; i++) {
        const int c = tid + i*256;
        O[row * D + c] = (h[i] - mean) * inv * g[c] + be[c];
    }
}

// ================= host launch =================
extern "C" void kernel_launch(void* const* d_in, const int* in_sizes, int n_in,
                              void* d_out, int out_size)
{
    const float* input = (const float*)d_in[0];
    const float* ctx   = (const float*)d_in[1];
    const float* mask  = (const float*)d_in[2];
    const float* cq_w = (const float*)d_in[3];  const float* cq_b = (const float*)d_in[4];
    const float* ck_w = (const float*)d_in[5];  const float* ck_b = (const float*)d_in[6];
    const float* cv_w = (const float*)d_in[7];  const float* cv_b = (const float*)d_in[8];
    const float* co_w = (const float*)d_in[9];  const float* co_b = (const float*)d_in[10];
    const float* co_g = (const float*)d_in[11]; const float* co_be= (const float*)d_in[12];
    const float* sq_w = (const float*)d_in[13]; const float* sq_b = (const float*)d_in[14];
    const float* sk_w = (const float*)d_in[15]; const float* sk_b = (const float*)d_in[16];
    const float* sv_w = (const float*)d_in[17]; const float* sv_b = (const float*)d_in[18];
    const float* so_w = (const float*)d_in[19]; const float* so_b = (const float*)d_in[20];
    const float* so_g = (const float*)d_in[21]; const float* so_be= (const float*)d_in[22];
    const float* fi_w = (const float*)d_in[23]; const float* fi_b = (const float*)d_in[24];
    const float* fo_w = (const float*)d_in[25]; const float* fo_b = (const float*)d_in[26];
    const float* fo_g = (const float*)d_in[27]; const float* fo_be= (const float*)d_in[28];

    float *q, *k, *v, *att, *x, *x2, *y, *inter;
    __nv_bfloat16 *sa, *sb;
    cudaGetSymbolAddress((void**)&q,    g_q);
    cudaGetSymbolAddress((void**)&k,    g_k);
    cudaGetSymbolAddress((void**)&v,    g_v);
    cudaGetSymbolAddress((void**)&att,  g_att);
    cudaGetSymbolAddress((void**)&x,    g_x);
    cudaGetSymbolAddress((void**)&x2,   g_x2);
    cudaGetSymbolAddress((void**)&y,    g_y);
    cudaGetSymbolAddress((void**)&inter,g_int);
    cudaGetSymbolAddress((void**)&sa,   g_sa);
    cudaGetSymbolAddress((void**)&sb,   g_sb);

    const float scale = 0.125f; // 1/sqrt(64)
    dim3 blk(256);
    const int FLASH_SMEM = (int)sizeof(FlashSmem);
    static int smem_set = 0;
    if (!smem_set) {
        cudaFuncSetAttribute(flash_attn_tc_kernel,
                             cudaFuncAttributeMaxDynamicSharedMemorySize, FLASH_SMEM);
        smem_set = 1;
    }

    #define SPLIT_A(X, R, C, SH)  split_a_kernel<<<((size_t)(R)*(C))/1024, blk>>>((X), sa, (C)-1, (SH))
    #define SPLIT_B(W, K_, N_, SH) split_b_kernel<<<((size_t)(K_)*(N_))/1024, blk>>>((W), sb, (K_), (N_)-1, (SH))
    #define GEMM(EPI, BIAS, OUT, M_, N_, K3)  hgemm_kernel<EPI><<<dim3((N_)/128, (M_)/128), blk>>>(sa, sb, (BIAS), (OUT), (N_), (K3))

    // ---- cross attention ----
    SPLIT_A(input, MQ, D, 10);
    SPLIT_B(cq_w, D, D, 10);  GEMM(0, cq_b, q, MQ, D, 3*D);
    SPLIT_A(ctx, MCTX, D, 10);
    SPLIT_B(ck_w, D, D, 10);  GEMM(0, ck_b, k, MCTX, D, 3*D);
    SPLIT_B(cv_w, D, D, 10);  GEMM(0, cv_b, v, MCTX, D, 3*D);

    flash_attn_tc_kernel<<<dim3(LQ/128, B*H), blk, FLASH_SMEM>>>(q, k, v, mask, att, LQ, LK, scale);

    SPLIT_A(att, MQ, D, 10);
    SPLIT_B(co_w, D, D, 10);  GEMM(0, co_b, y, MQ, D, 3*D);
    ln_residual_kernel<<<MQ, blk>>>(y, input, co_g, co_be, x);

    // ---- self attention ----
    SPLIT_A(x, MQ, D, 10);
    SPLIT_B(sq_w, D, D, 10);  GEMM(0, sq_b, q, MQ, D, 3*D);
    SPLIT_B(sk_w, D, D, 10);  GEMM(0, sk_b, k, MQ, D, 3*D);
    SPLIT_B(sv_w, D, D, 10);  GEMM(0, sv_b, v, MQ, D, 3*D);

    flash_attn_tc_kernel<<<dim3(LQ/128, B*H), blk, FLASH_SMEM>>>(q, k, v, nullptr, att, LQ, LQ, scale);

    SPLIT_A(att, MQ, D, 10);
    SPLIT_B(so_w, D, D, 10);  GEMM(0, so_b, y, MQ, D, 3*D);
    ln_residual_kernel<<<MQ, blk>>>(y, x, so_g, so_be, x2);

    // ---- FFN ----
    SPLIT_A(x2, MQ, D, 10);
    SPLIT_B(fi_w, D, F, 12);  GEMM(1, fi_b, inter, MQ, F, 3*D);
    SPLIT_A(inter, MQ, F, 12);
    SPLIT_B(fo_w, F, D, 10);  GEMM(0, fo_b, y, MQ, D, 3*F);
    ln_residual_kernel<<<MQ, blk>>>(y, x2, fo_g, fo_be, (float*)d_out);

    #undef SPLIT_A
    #undef SPLIT_B
    #undef GEMM
}